// round 14
// baseline (speedup 1.0000x reference)
#include <cuda_runtime.h>
#include <math.h>

#define DD    40
#define SLAB  1600           // 40*40 slab elements
#define NVOX  64000          // 40*40*40
#define NB    2
#define KP    2048
#define EPSV  2.0f
#define BIGF  1e12f
#define SENT  1e9f           // real d2 <= 3*39^2 = 4563 << SENT << BIGF
#define NBLK1 80             // k1: one block per (b,z) slab
#define TPB1  512
#define NTASK 400            // k1 active tasks (4 outputs each)
#define NBLK2 125            // k2: 125*256 = 32000 threads, all active
#define TPB2  256

// Scratch (no cudaMalloc allowed)
__device__ float  g_B[NB*NVOX];   // after X+Y passes
__device__ float  g_C[NB*NVOX];   // final per-voxel 1-NN d^2 (fallback only)
__device__ double g_bsum[NB];
__device__ int    g_bcnt[NB];

// ======================= Kernel 1: slab X + Y passes =======================
__global__ void __launch_bounds__(TPB1, 1)
k_passXY(const float* __restrict__ tgt) {
    const int t = threadIdx.x;
    __shared__ float s0[SLAB];
    __shared__ float s1[SLAB];

    if (blockIdx.x == 0 && t == 0) {      // re-init accumulators every replay
        g_bsum[0] = 0.0; g_bsum[1] = 0.0;
        g_bcnt[0] = 0;   g_bcnt[1] = 0;
    }

    const int b = blockIdx.x / DD;
    const int z = blockIdx.x - b * DD;
    const int slabBase = b * NVOX + z * SLAB;

    // seeds from target>0 (float4 loads, 400 threads cover 1600 floats)
    if (t < NTASK) {
        float4 v = reinterpret_cast<const float4*>(tgt + slabBase)[t];
        float4 s;
        s.x = (v.x > 0.0f) ? 0.0f : BIGF;
        s.y = (v.y > 0.0f) ? 0.0f : BIGF;
        s.z = (v.z > 0.0f) ? 0.0f : BIGF;
        s.w = (v.w > 0.0f) ? 0.0f : BIGF;
        reinterpret_cast<float4*>(s0)[t] = s;
    }
    __syncthreads();

    // pass X: rows along x, s0 -> s1
    if (t < NTASK) {
        int row = t / 10;                 // y
        int i0  = (t - row * 10) * 4;
        const float* f = s0 + row * DD;
        float m0 = 4e12f, m1 = 4e12f, m2 = 4e12f, m3 = 4e12f;
        #pragma unroll
        for (int j = 0; j < DD; j++) {
            float v = f[j];
            float d = (float)(i0 - j);
            m0 = fminf(m0, fmaf(d,       d,       v));
            m1 = fminf(m1, fmaf(d + 1.f, d + 1.f, v));
            m2 = fminf(m2, fmaf(d + 2.f, d + 2.f, v));
            m3 = fminf(m3, fmaf(d + 3.f, d + 3.f, v));
        }
        reinterpret_cast<float4*>(s1 + row * DD)[i0 >> 2] = make_float4(m0, m1, m2, m3);
    }
    __syncthreads();

    // pass Y: columns along y, s1 -> g_B (conflict-free smem reads, coalesced writes)
    if (t < NTASK) {
        int grp = t / DD;                 // y0/4
        int x   = t - grp * DD;
        int y0  = grp * 4;
        float m0 = 4e12f, m1 = 4e12f, m2 = 4e12f, m3 = 4e12f;
        #pragma unroll
        for (int j = 0; j < DD; j++) {
            float v = s1[j * DD + x];
            float d = (float)(y0 - j);
            m0 = fminf(m0, fmaf(d,       d,       v));
            m1 = fminf(m1, fmaf(d + 1.f, d + 1.f, v));
            m2 = fminf(m2, fmaf(d + 2.f, d + 2.f, v));
            m3 = fminf(m3, fmaf(d + 3.f, d + 3.f, v));
        }
        float* o = g_B + slabBase + x;
        o[(y0    ) * DD] = m0;
        o[(y0 + 1) * DD] = m1;
        o[(y0 + 2) * DD] = m2;
        o[(y0 + 3) * DD] = m3;
    }
}

// ========== Kernel 2: Z pass + pred reduction (no fence, no ticket) ==========
__global__ void __launch_bounds__(TPB2, 1)
k_passZ_reduce(const float* __restrict__ inp) {
    const int t = threadIdx.x;
    __shared__ double rs0[8], rs1[8];
    __shared__ int    rc0[8], rc1[8];
    const int lane = t & 31, wid = t >> 5;

    double ls0 = 0.0, ls1 = 0.0;
    int    lc0 = 0,   lc1 = 0;
    {
        int t2 = blockIdx.x * TPB2 + t;       // 0..31999, all active
        int g  = t2 / 3200;                   // z-group
        int c  = t2 - g * 3200;               // b*1600 + y*40 + x
        int bb = c / SLAB;
        int yx = c - bb * SLAB;
        int colBase = bb * NVOX + yx;
        int z0 = g * 4;
        float m0 = 4e12f, m1 = 4e12f, m2 = 4e12f, m3 = 4e12f;
        #pragma unroll 8
        for (int j = 0; j < DD; j++) {
            float v = g_B[colBase + j * SLAB];
            float d = (float)(z0 - j);
            m0 = fminf(m0, fmaf(d,       d,       v));
            m1 = fminf(m1, fmaf(d + 1.f, d + 1.f, v));
            m2 = fminf(m2, fmaf(d + 2.f, d + 2.f, v));
            m3 = fminf(m3, fmaf(d + 3.f, d + 3.f, v));
        }
        float mv[4] = {m0, m1, m2, m3};
        #pragma unroll
        for (int k = 0; k < 4; k++) {
            int idx = colBase + (z0 + k) * SLAB;
            float d2 = mv[k];
            g_C[idx] = d2;                    // raw d^2, for >KP fallback only
            if (inp[idx] > EPSV) {            // sqrt only on pred voxels
                float dist = (d2 > SENT) ? 0.0f : sqrtf(fmaxf(d2, 0.0f));
                if (bb == 0) { ls0 += (double)dist; lc0++; }
                else         { ls1 += (double)dist; lc1++; }
            }
        }
    }
    // block reduce, then one atomic set per block (125 atomics/address total)
    #pragma unroll
    for (int o = 16; o > 0; o >>= 1) {
        ls0 += __shfl_down_sync(0xFFFFFFFFu, ls0, o);
        ls1 += __shfl_down_sync(0xFFFFFFFFu, ls1, o);
        lc0 += __shfl_down_sync(0xFFFFFFFFu, lc0, o);
        lc1 += __shfl_down_sync(0xFFFFFFFFu, lc1, o);
    }
    if (lane == 0) { rs0[wid] = ls0; rs1[wid] = ls1; rc0[wid] = lc0; rc1[wid] = lc1; }
    __syncthreads();
    if (t == 0) {
        double a0 = 0.0, a1 = 0.0; int c0 = 0, c1 = 0;
        #pragma unroll
        for (int w = 0; w < 8; w++) { a0 += rs0[w]; a1 += rs1[w]; c0 += rc0[w]; c1 += rc1[w]; }
        if (c0) { atomicAdd(&g_bsum[0], a0); atomicAdd(&g_bcnt[0], c0); }
        if (c1) { atomicAdd(&g_bsum[1], a1); atomicAdd(&g_bcnt[1], c1); }
    }
    // exit — the k3 launch boundary provides all ordering we need
}

// ============ Kernel 3: finalize (1 block) — fallback + mean write ============
__global__ void __launch_bounds__(TPB1, 1)
k_finalize(const float* __restrict__ inp, float* __restrict__ out) {
    const int t = threadIdx.x;
    __shared__ double rs[16];
    __shared__ int    rc[16];
    __shared__ int    warpSums[16];
    const int lane = t & 31, wid = t >> 5;

    // >KP ordered-truncation fallback (first-2048-in-flat-order, matching
    // jnp.nonzero(size=KP)); never taken in practice but exact if it is.
    for (int bb = 0; bb < NB; bb++) {
        if (g_bcnt[bb] <= KP) continue;
        int runningBase = 0;
        double lsum = 0.0; int lcnt = 0;
        for (int chunk = 0; chunk < NVOX; chunk += TPB1) {   // 64000 % 512 == 0
            int idx = chunk + t;
            bool pred = inp[bb * NVOX + idx] > EPSV;
            unsigned ball = __ballot_sync(0xFFFFFFFFu, pred);
            int lanePre = __popc(ball & ((1u << lane) - 1u));
            if (lane == 0) warpSums[wid] = __popc(ball);
            __syncthreads();
            int wOff = 0, total = 0;
            #pragma unroll
            for (int w = 0; w < 16; w++) {
                int cc = warpSums[w];
                if (w < wid) wOff += cc;
                total += cc;
            }
            int rank = runningBase + wOff + lanePre;
            if (pred && rank < KP) {
                lcnt++;
                float d2 = g_C[bb * NVOX + idx];
                lsum += (d2 > SENT) ? 0.0 : (double)sqrtf(fmaxf(d2, 0.0f));
            }
            runningBase += total;
            __syncthreads();
        }
        #pragma unroll
        for (int o = 16; o > 0; o >>= 1) {
            lsum += __shfl_down_sync(0xFFFFFFFFu, lsum, o);
            lcnt += __shfl_down_sync(0xFFFFFFFFu, lcnt, o);
        }
        if (lane == 0) { rs[wid] = lsum; rc[wid] = lcnt; }
        __syncthreads();
        if (t == 0) {
            double s = 0.0; int cn = 0;
            #pragma unroll
            for (int w = 0; w < 16; w++) { s += rs[w]; cn += rc[w]; }
            g_bsum[bb] = s;               // overwrite fast-path value
            g_bcnt[bb] = cn;
        }
        __syncthreads();
    }

    if (t == 0) {
        int    cnt = g_bcnt[0] + g_bcnt[1];
        double s   = g_bsum[0] + g_bsum[1];
        out[0] = (cnt > 0) ? (float)(s / (double)cnt) : 0.0f;
    }
}

extern "C" void kernel_launch(void* const* d_in, const int* in_sizes, int n_in,
                              void* d_out, int out_size) {
    const float* inp = (const float*)d_in[0];   // "input"  [2,40,40,40]
    const float* tgt = (const float*)d_in[1];   // "target" [2,40,40,40]
    float* out = (float*)d_out;
    k_passXY<<<NBLK1, TPB1>>>(tgt);
    k_passZ_reduce<<<NBLK2, TPB2>>>(inp);
    k_finalize<<<1, TPB1>>>(inp, out);
}

// round 15
// speedup vs baseline: 1.1359x; 1.1359x over previous
#include <cuda_runtime.h>
#include <math.h>

#define DD    40
#define SLAB  1600           // 40*40
#define NVOX  64000          // 40^3
#define NB    2
#define KP    2048
#define EPSV  2.0f
#define BIGF  1e12f
#define SENT  1e9f           // real d2 <= 3*39^2 = 4563 << SENT << BIGF
#define TPBM  1024
#define NBLKM 125            // 125*1024 = 128000 = NB*NVOX, all threads active
#define TPBF  512

// Accumulators only — no voxel-grid scratch needed at all.
__device__ double g_bsum[NB];
__device__ int    g_bcnt[NB];

// ---- exact expanding-shell continuation for r >= 2 (cold: P ~ 2^-27) ----
__device__ __noinline__ float nn_d2_from(const float* __restrict__ t,
                                         int z, int y, int x, float m) {
    for (int r = 2; r <= 39; r++) {
        if (m <= (float)(r * r)) break;      // remaining shells have d2 >= r^2
        for (int dz = -r; dz <= r; dz++) {
            int zz = z + dz; if (zz < 0 || zz > 39) continue;
            bool zface = (dz == -r) || (dz == r);
            for (int dy = -r; dy <= r; dy++) {
                int yy = y + dy; if (yy < 0 || yy > 39) continue;
                bool face = zface || (dy == -r) || (dy == r);
                int rowbase = zz * SLAB + yy * DD;
                int d2zy = dz * dz + dy * dy;
                if (face) {
                    for (int dx = -r; dx <= r; dx++) {
                        int xx = x + dx; if (xx < 0 || xx > 39) continue;
                        if (t[rowbase + xx] > 0.0f)
                            m = fminf(m, (float)(d2zy + dx * dx));
                    }
                } else {
                    int xx = x - r;
                    if (xx >= 0 && t[rowbase + xx] > 0.0f)
                        m = fminf(m, (float)(d2zy + r * r));
                    xx = x + r;
                    if (xx <= 39 && t[rowbase + xx] > 0.0f)
                        m = fminf(m, (float)(d2zy + r * r));
                }
            }
        }
    }
    return m;
}

// ---- exact nearest-true d^2: hot unrolled 3x3x3, then cold generic tail ----
__device__ __forceinline__ float nn_d2_exact(const float* __restrict__ t,
                                             int z, int y, int x) {
    int v = z * SLAB + y * DD + x;
    if (t[v] > 0.0f) return 0.0f;            // P = 0.5: done immediately
    float m = BIGF;
    bool zm = z > 0, zp = z < 39, ym = y > 0, yp = y < 39, xm = x > 0, xp = x < 39;
    #pragma unroll
    for (int dz = -1; dz <= 1; dz++) {
        #pragma unroll
        for (int dy = -1; dy <= 1; dy++) {
            #pragma unroll
            for (int dx = -1; dx <= 1; dx++) {
                if (dz == 0 && dy == 0 && dx == 0) continue;
                bool ok = (dz >= 0 || zm) && (dz <= 0 || zp)
                       && (dy >= 0 || ym) && (dy <= 0 || yp)
                       && (dx >= 0 || xm) && (dx <= 0 || xp);
                if (ok && t[v + dz * SLAB + dy * DD + dx] > 0.0f)
                    m = fminf(m, (float)(dz * dz + dy * dy + dx * dx));
            }
        }
    }
    // if any seed in the 27-cube, m <= 3 < 4 <= d2 of everything outside -> exact
    if (m > 3.5f) m = nn_d2_from(t, z, y, x, m);
    return m;
}

// =============== Kernel 1: pred-gated search + reduction ===============
__global__ void __launch_bounds__(TPBM, 1)
k_main(const float* __restrict__ inp, const float* __restrict__ tgt) {
    const int t = threadIdx.x;
    const int idx = blockIdx.x * TPBM + t;   // 0..127999, all active
    __shared__ double rs0[32], rs1[32];
    __shared__ int    rc0[32], rc1[32];

    double ls0 = 0.0, ls1 = 0.0;
    int    lc0 = 0,   lc1 = 0;

    // warp spans 32 consecutive idx; NVOX % 32 == 0 so b is warp-uniform
    int b = idx / NVOX;
    int v = idx - b * NVOX;
    if (inp[idx] > EPSV) {                   // ~2.3% of lanes
        int z = v / SLAB;
        int rem = v - z * SLAB;
        int y = rem / DD;
        int x = rem - y * DD;
        float m = nn_d2_exact(tgt + b * NVOX, z, y, x);
        float dist = (m > SENT) ? 0.0f : sqrtf(m);   // no-true batch -> 0, still counted
        if (b == 0) { ls0 += (double)dist; lc0++; }
        else        { ls1 += (double)dist; lc1++; }
    }

    #pragma unroll
    for (int o = 16; o > 0; o >>= 1) {
        ls0 += __shfl_down_sync(0xFFFFFFFFu, ls0, o);
        ls1 += __shfl_down_sync(0xFFFFFFFFu, ls1, o);
        lc0 += __shfl_down_sync(0xFFFFFFFFu, lc0, o);
        lc1 += __shfl_down_sync(0xFFFFFFFFu, lc1, o);
    }
    int lane = t & 31, wid = t >> 5;
    if (lane == 0) { rs0[wid] = ls0; rs1[wid] = ls1; rc0[wid] = lc0; rc1[wid] = lc1; }
    __syncthreads();
    if (t == 0) {
        double a0 = 0.0, a1 = 0.0; int c0 = 0, c1 = 0;
        #pragma unroll
        for (int w = 0; w < 32; w++) { a0 += rs0[w]; a1 += rs1[w]; c0 += rc0[w]; c1 += rc1[w]; }
        if (c0) { atomicAdd(&g_bsum[0], a0); atomicAdd(&g_bcnt[0], c0); }
        if (c1) { atomicAdd(&g_bsum[1], a1); atomicAdd(&g_bcnt[1], c1); }
    }
}

// ========== Kernel 2: finalize — >KP fallback, mean, replay reset ==========
__global__ void __launch_bounds__(TPBF, 1)
k_finalize(const float* __restrict__ inp, const float* __restrict__ tgt,
           float* __restrict__ out) {
    const int t = threadIdx.x;
    __shared__ double rs[16];
    __shared__ int    rc[16];
    __shared__ int    warpSums[16];
    const int lane = t & 31, wid = t >> 5;

    // Ordered-truncation fallback: first-2048-in-flat-order, matching
    // jnp.nonzero(size=KP). Never taken in practice (predCount ~1456, 15 sigma
    // below KP) but exact if it is.
    for (int bb = 0; bb < NB; bb++) {
        if (g_bcnt[bb] <= KP) continue;
        const float* tg = tgt + bb * NVOX;
        int runningBase = 0;
        double lsum = 0.0; int lcnt = 0;
        for (int chunk = 0; chunk < NVOX; chunk += TPBF) {   // 64000 % 512 == 0
            int idx = chunk + t;
            bool pred = inp[bb * NVOX + idx] > EPSV;
            unsigned ball = __ballot_sync(0xFFFFFFFFu, pred);
            int lanePre = __popc(ball & ((1u << lane) - 1u));
            if (lane == 0) warpSums[wid] = __popc(ball);
            __syncthreads();
            int wOff = 0, total = 0;
            #pragma unroll
            for (int w = 0; w < 16; w++) {
                int cc = warpSums[w];
                if (w < wid) wOff += cc;
                total += cc;
            }
            int rank = runningBase + wOff + lanePre;
            if (pred && rank < KP) {
                lcnt++;
                int z = idx / SLAB;
                int rem = idx - z * SLAB;
                int y = rem / DD;
                int x = rem - y * DD;
                float m = nn_d2_exact(tg, z, y, x);
                lsum += (m > SENT) ? 0.0 : (double)sqrtf(m);
            }
            runningBase += total;
            __syncthreads();
        }
        #pragma unroll
        for (int o = 16; o > 0; o >>= 1) {
            lsum += __shfl_down_sync(0xFFFFFFFFu, lsum, o);
            lcnt += __shfl_down_sync(0xFFFFFFFFu, lcnt, o);
        }
        if (lane == 0) { rs[wid] = lsum; rc[wid] = lcnt; }
        __syncthreads();
        if (t == 0) {
            double s = 0.0; int cn = 0;
            #pragma unroll
            for (int w = 0; w < 16; w++) { s += rs[w]; cn += rc[w]; }
            g_bsum[bb] = s;               // overwrite fast-path value
            g_bcnt[bb] = cn;
        }
        __syncthreads();
    }

    if (t == 0) {
        int    cnt = g_bcnt[0] + g_bcnt[1];
        double s   = g_bsum[0] + g_bsum[1];
        out[0] = (cnt > 0) ? (float)(s / (double)cnt) : 0.0f;
        // reset accumulators so the next graph replay starts clean
        g_bsum[0] = 0.0; g_bsum[1] = 0.0;
        g_bcnt[0] = 0;   g_bcnt[1] = 0;
    }
}

extern "C" void kernel_launch(void* const* d_in, const int* in_sizes, int n_in,
                              void* d_out, int out_size) {
    const float* inp = (const float*)d_in[0];   // "input"  [2,40,40,40]
    const float* tgt = (const float*)d_in[1];   // "target" [2,40,40,40]
    float* out = (float*)d_out;
    k_main<<<NBLKM, TPBM>>>(inp, tgt);
    k_finalize<<<1, TPBF>>>(inp, tgt, out);
}